// round 14
// baseline (speedup 1.0000x reference)
#include <cuda_runtime.h>
#include <math.h>

#define BATCH 2
#define MP 40
#define MG 24
#define NPT 24
#define NRS 64
#define Hh 72
#define Ww 128
#define GRID_N (Hh*Ww)      // 9216
#define NPAIR (BATCH*MP*MG) // 1920
#define BIG2 1e18f
#define THICKF 0.03f
#define SHARPF 80.0f

// mask decomposition: 18 chunks x 4 rows
#define MCHUNKS 18
#define MROWS 4

// ---------------- device scratch ----------------
__device__ float g_prs [BATCH*MP*NRS*2];
__device__ float g_grs [BATCH*MG*NRS*2];
__device__ float g_ptan[BATCH*MP*NRS*2];
__device__ float g_gtan[BATCH*MG*NRS*2];
__device__ float g_pmask[BATCH*MP*GRID_N];
__device__ float g_gmask[BATCH*MG*GRID_N];
__device__ float g_partial[NPAIR];
__device__ float g_inter[NPAIR];
__device__ float g_msum[128];

__device__ __forceinline__ float sl1(float d) {
    d = fabsf(d);
    return d < 1.f ? 0.5f*d*d : d - 0.5f;
}

// =====================================================================
// Kernel A (128 threads/block, 2432 blocks):
//   blocks 0..127:    resample + tangents (one curve per block)
//   blocks 128..2431: soft masks; curve=(bid-128)/18, chunk=(bid-128)%18,
//                     4 rows per thread (high occupancy)
//   zeroes g_inter and g_msum for kernel B
// =====================================================================
__global__ void __launch_bounds__(128, 14)
k_A(const float* __restrict__ pred,
    const float* __restrict__ gt,
    const float* __restrict__ vis) {
    int bid = blockIdx.x, tid = threadIdx.x;
    int gtid = bid*128 + tid;
    if (gtid < NPAIR) g_inter[gtid] = 0.f;
    if (gtid >= NPAIR && gtid < NPAIR + 128) g_msum[gtid - NPAIR] = 0.f;

    if (bid < 128) {
        // ---------------- resample + tangents ----------------
        __shared__ float px[NPT], py[NPT], pm[NPT], cum[NPT];
        __shared__ float ox[NRS], oy[NRS];
        int cid = bid;
        bool isPred = cid < BATCH*MP;
        const float* src; float *dst_rs, *dst_tan; int b, c;
        if (isPred) {
            b = cid / MP; c = cid % MP;
            src = pred + (b*MP + c)*NPT*2;
            dst_rs  = g_prs  + (b*MP + c)*NRS*2;
            dst_tan = g_ptan + (b*MP + c)*NRS*2;
        } else {
            int q = cid - BATCH*MP;
            b = q / MG; c = q % MG;
            src = gt + (b*MG + c)*NPT*2;
            dst_rs  = g_grs  + (b*MG + c)*NRS*2;
            dst_tan = g_gtan + (b*MG + c)*NRS*2;
        }
        if (tid < NPT) {
            px[tid] = src[tid*2];
            py[tid] = src[tid*2+1];
            pm[tid] = isPred ? 1.0f : (vis[(b*MG+c)*NPT + tid] > 0.5f ? 1.0f : 0.0f);
        }
        __syncthreads();
        if (tid == 0) {
            if (!isPred) {
                int cnt = 0;
                for (int k = 0; k < NPT; k++) cnt += (pm[k] > 0.5f);
                if (cnt < 2) for (int k = 0; k < NPT; k++) pm[k] = 1.0f;
            }
            float s = 0.f; cum[0] = 0.f;
            for (int k = 0; k < NPT-1; k++) {
                float dx = px[k+1]-px[k], dy = py[k+1]-py[k];
                s += sqrtf(dx*dx+dy*dy) * (pm[k]*pm[k+1]);
                cum[k+1] = s;
            }
        }
        __syncthreads();
        if (tid < NRS) {
            float total = cum[NPT-1];
            float qx, qy;
            if (total < 1e-8f) { qx = px[0]; qy = py[0]; }
            else {
                float t = (tid == NRS-1) ? total : tid * (1.0f/(NRS-1)) * total;
                int cnt = 0;
                for (int k = 0; k < NPT; k++) cnt += (cum[k] <= t);
                int idx = cnt - 1;
                if (idx > NPT-2) idx = NPT-2;
                if (idx < 0)     idx = 0;
                float lt = cum[idx], rt = cum[idx+1];
                float alpha = (t - lt) / fmaxf(rt - lt, 1e-8f);
                qx = px[idx] + alpha*(px[idx+1]-px[idx]);
                qy = py[idx] + alpha*(py[idx+1]-py[idx]);
            }
            ox[tid] = qx; oy[tid] = qy;
            dst_rs[tid*2]   = qx;
            dst_rs[tid*2+1] = qy;
        }
        __syncthreads();
        if (tid < NRS) {
            int a = (tid == 0)     ? 0     : tid-1;
            int e = (tid == NRS-1) ? NRS-1 : tid+1;
            float fx = ox[e]-ox[a], fy = oy[e]-oy[a];
            float nr = fmaxf(sqrtf(fx*fx+fy*fy), 1e-8f);
            dst_tan[tid*2]   = fx/nr;
            dst_tan[tid*2+1] = fy/nr;
        }
    } else {
        // ---------------- soft mask: column-constant X, 4 rows/thread ----------------
        int mb = bid - 128;
        int cid = mb / MCHUNKS, chunk = mb % MCHUNKS;
        __shared__ float px[NPT], py[NPT], pm[NPT], sppen[NPT];
        __shared__ __align__(16) float4 s4a[NPT-1];
        __shared__ __align__(16) float4 s4b[NPT-1];
        __shared__ int s_any;

        bool isPred = cid < BATCH*MP;
        const float* src; float* dst; int b, c;
        if (isPred) {
            b = cid/MP; c = cid%MP;
            src = pred + (b*MP+c)*NPT*2;
            dst = g_pmask + (b*MP+c)*GRID_N;
        } else {
            int q = cid - BATCH*MP;
            b = q/MG; c = q%MG;
            src = gt + (b*MG+c)*NPT*2;
            dst = g_gmask + (b*MG+c)*GRID_N;
        }
        if (tid < NPT) {
            px[tid] = src[tid*2];
            py[tid] = src[tid*2+1];
            pm[tid] = isPred ? 1.f : (vis[(b*MG+c)*NPT+tid] > 0.5f ? 1.f : 0.f);
        }
        __syncthreads();
        if (tid == 0) {
            if (!isPred) {
                int cnt = 0;
                for (int k = 0; k < NPT; k++) cnt += (pm[k] > 0.5f);
                if (cnt < 2) for (int k = 0; k < NPT; k++) pm[k] = 1.f;
            }
            int any = 0;
            for (int k = 0; k < NPT-1; k++) any |= (pm[k]*pm[k+1] > 0.5f);
            s_any = any;
        }
        __syncthreads();
        if (tid < NPT-1) {
            float ax = px[tid], ay = py[tid];
            float abx = px[tid+1]-ax, aby = py[tid+1]-ay;
            float inv = 1.0f / fmaxf(abx*abx + aby*aby, 1e-8f);
            s4a[tid] = make_float4(ax, ay, abx, aby);
            s4b[tid] = make_float4(abx*inv, aby*inv, (ax*abx + ay*aby)*inv,
                                   (pm[tid]*pm[tid+1] > 0.5f) ? 0.f : BIG2);
        }
        if (tid < NPT) sppen[tid] = (pm[tid] > 0.5f) ? 0.f : BIG2;
        __syncthreads();

        float X = tid * (1.0f/(Ww-1));
        int row0 = chunk*MROWS;
        float m[MROWS];
        #pragma unroll
        for (int k = 0; k < MROWS; k++) m[k] = BIG2;

        if (s_any) {
            #pragma unroll 1
            for (int s = 0; s < NPT-1; s++) {
                float4 A = s4a[s];
                float4 B = s4b[s];
                float e   = fmaf(X, B.x, -B.z);
                float dxs = X - A.x;
                #pragma unroll
                for (int k = 0; k < MROWS; k++) {
                    float Y = (row0 + k) * (1.0f/(Hh-1));
                    float t = __saturatef(fmaf(Y, B.y, e));
                    float dx = fmaf(-t, A.z, dxs);
                    float dy = fmaf(-t, A.w, Y - A.y);
                    float d2 = fmaf(dy, dy, fmaf(dx, dx, B.w));
                    m[k] = fminf(m[k], d2);
                }
            }
        } else {
            #pragma unroll 1
            for (int p = 0; p < NPT; p++) {
                float ax = px[p], ay = py[p];
                float dxs = X - ax;
                float sxp = fmaf(dxs, dxs, sppen[p]);
                #pragma unroll
                for (int k = 0; k < MROWS; k++) {
                    float dy = (row0 + k) * (1.0f/(Hh-1)) - ay;
                    m[k] = fminf(m[k], fmaf(dy, dy, sxp));
                }
            }
        }
        #pragma unroll
        for (int k = 0; k < MROWS; k++) {
            float z = (THICKF - sqrtf(m[k])) * SHARPF;
            dst[(row0 + k)*128 + tid] = __fdividef(1.0f, 1.0f + __expf(-z));
        }
    }
    cudaTriggerProgrammaticLaunchCompletion();
}

// =====================================================================
// Kernel B (768 blocks x 256 thr):
//   [blocks 0..479]   pairwise sym/tan/curv (4 pairs per block)
//   [blocks 480..767] IoU min-sums (64-pt chunks, 2x2 tiling) + msum
// =====================================================================
#define GSTRIDE 1272
__global__ void __launch_bounds__(256, 6)
k_B() {
    __shared__ __align__(16) float sm[4*GSTRIDE];   // 20352 B
    int bid = blockIdx.x, tid = threadIdx.x;

    cudaGridDependencySynchronize();   // wait for k_A's writes to be visible

    if (bid < 480) {
        // ---------------- pair costs ----------------
        int grp = tid >> 6, n = tid & 63;
        int pid = bid*4 + grp;
        int b = pid / (MP*MG);
        int r = pid % (MP*MG);
        int i = r / MG, j = r % MG;

        float* gp  = sm + grp*GSTRIDE;
        float* spx = gp;        float* spy = gp + 64;
        float* sgx = gp + 128;  float* sgy = gp + 192;
        float4* psa = (float4*)(gp + 256);
        float4* psb = (float4*)(gp + 508);
        float4* gsa = (float4*)(gp + 760);
        float4* gsb = (float4*)(gp + 1012);
        float* red  = gp + 1264;

        const float* pr = g_prs + (b*MP+i)*NRS*2;
        const float* gr = g_grs + (b*MG+j)*NRS*2;
        spx[n] = pr[2*n]; spy[n] = pr[2*n+1];
        sgx[n] = gr[2*n]; sgy[n] = gr[2*n+1];

        const float* pt  = g_ptan + (b*MP+i)*NRS*2;
        const float* gtt = g_gtan + (b*MG+j)*NRS*2;
        float ptx_ = pt[2*n],  pty_ = pt[2*n+1];
        float gtx_ = gtt[2*n], gty_ = gtt[2*n+1];

        __syncthreads();
        if (n < NRS-1) {
            float ax = spx[n], ay = spy[n];
            float abx = spx[n+1]-ax, aby = spy[n+1]-ay;
            float inv = 1.0f / fmaxf(abx*abx+aby*aby, 1e-8f);
            psa[n] = make_float4(ax, ay, abx, aby);
            psb[n] = make_float4(abx*inv, aby*inv, (ax*abx+ay*aby)*inv, 0.f);
            ax = sgx[n]; ay = sgy[n];
            abx = sgx[n+1]-ax; aby = sgy[n+1]-ay;
            inv = 1.0f / fmaxf(abx*abx+aby*aby, 1e-8f);
            gsa[n] = make_float4(ax, ay, abx, aby);
            gsb[n] = make_float4(abx*inv, aby*inv, (ax*abx+ay*aby)*inv, 0.f);
        }
        __syncthreads();

        float qx = spx[n], qy = spy[n], ux = sgx[n], uy = sgy[n];
        float da2a = BIG2, da2b = BIG2, db2a = BIG2, db2b = BIG2;
        #pragma unroll 2
        for (int s = 0; s < NRS-2; s += 2) {
            {
                float4 A = gsa[s], B = gsb[s];
                float t = __saturatef(fmaf(qy, B.y, fmaf(qx, B.x, -B.z)));
                float dx = fmaf(-t, A.z, qx - A.x);
                float dy = fmaf(-t, A.w, qy - A.y);
                da2a = fminf(da2a, fmaf(dy, dy, dx*dx));
            }
            {
                float4 A = psa[s], B = psb[s];
                float t = __saturatef(fmaf(uy, B.y, fmaf(ux, B.x, -B.z)));
                float dx = fmaf(-t, A.z, ux - A.x);
                float dy = fmaf(-t, A.w, uy - A.y);
                db2a = fminf(db2a, fmaf(dy, dy, dx*dx));
            }
            {
                float4 A = gsa[s+1], B = gsb[s+1];
                float t = __saturatef(fmaf(qy, B.y, fmaf(qx, B.x, -B.z)));
                float dx = fmaf(-t, A.z, qx - A.x);
                float dy = fmaf(-t, A.w, qy - A.y);
                da2b = fminf(da2b, fmaf(dy, dy, dx*dx));
            }
            {
                float4 A = psa[s+1], B = psb[s+1];
                float t = __saturatef(fmaf(uy, B.y, fmaf(ux, B.x, -B.z)));
                float dx = fmaf(-t, A.z, ux - A.x);
                float dy = fmaf(-t, A.w, uy - A.y);
                db2b = fminf(db2b, fmaf(dy, dy, dx*dx));
            }
        }
        {   // tail segment s = 62
            const int s = NRS-2;
            {
                float4 A = gsa[s], B = gsb[s];
                float t = __saturatef(fmaf(qy, B.y, fmaf(qx, B.x, -B.z)));
                float dx = fmaf(-t, A.z, qx - A.x);
                float dy = fmaf(-t, A.w, qy - A.y);
                da2a = fminf(da2a, fmaf(dy, dy, dx*dx));
            }
            {
                float4 A = psa[s], B = psb[s];
                float t = __saturatef(fmaf(uy, B.y, fmaf(ux, B.x, -B.z)));
                float dx = fmaf(-t, A.z, ux - A.x);
                float dy = fmaf(-t, A.w, uy - A.y);
                db2a = fminf(db2a, fmaf(dy, dy, dx*dx));
            }
        }
        float dd = sqrtf(fminf(da2a, da2b)) + sqrtf(fminf(db2a, db2b));

        float td = fabsf(ptx_*gtx_ + pty_*gty_);

        float cv = 0.f;
        if (n < NRS-2) {
            float psx = spx[n+2] - 2.f*spx[n+1] + spx[n];
            float psy = spy[n+2] - 2.f*spy[n+1] + spy[n];
            float gsxv = sgx[n+2] - 2.f*sgx[n+1] + sgx[n];
            float gsyv = sgy[n+2] - 2.f*sgy[n+1] + sgy[n];
            cv = sl1(psx-gsxv) + sl1(psy-gsyv);
        }
        unsigned msk = 0xffffffffu;
        #pragma unroll
        for (int o = 16; o; o >>= 1) {
            dd += __shfl_down_sync(msk, dd, o);
            td += __shfl_down_sync(msk, td, o);
            cv += __shfl_down_sync(msk, cv, o);
        }
        int w = (n >> 5), l = n & 31;
        if (l == 0) { red[w*3+0]=dd; red[w*3+1]=td; red[w*3+2]=cv; }
        __syncthreads();
        if (n == 0) {
            float sdd  = red[0] + red[3];
            float std_ = red[1] + red[4];
            float scv  = red[2] + red[5];
            float sym  = 0.5f * sdd * (1.0f/NRS);
            float tanv = 1.0f - std_ * (1.0f/NRS);
            float curv = scv * (1.0f/((NRS-2)*2));
            g_partial[pid] = 5.0f*sym + 1.0f*tanv + 0.5f*curv;
        }
    } else {
        // ---------------- IoU min-sums over 64-pt grid chunk ----------------
        int blk = bid - 480;
        int b  = blk / 144;
        int ch = blk % 144;
        int gbase = ch * 64;

        for (int idx = tid; idx < 64*64; idx += 256) {
            int c = idx >> 6, g = idx & 63;
            float v = (c < MP) ? g_pmask[(b*MP + c)*GRID_N + gbase + g]
                               : g_gmask[(b*MG + (c-MP))*GRID_N + gbase + g];
            sm[c*68 + g] = v;
        }
        __syncthreads();

        if (tid < 64) {
            const float4* row = (const float4*)(sm + tid*68);
            float s = 0.f;
            #pragma unroll
            for (int q = 0; q < 16; q++) {
                float4 v = row[q];
                s += (v.x + v.y) + (v.z + v.w);
            }
            int mi = (tid < MP) ? (b*MP + tid) : (BATCH*MP + b*MG + (tid - MP));
            atomicAdd(&g_msum[mi], s);
        }

        if (tid < 240) {
            int i0 = tid / 12, j0 = tid % 12;
            const float4* a0 = (const float4*)(sm + i0*68);
            const float4* a1 = (const float4*)(sm + (i0+20)*68);
            const float4* b0 = (const float4*)(sm + (MP+j0)*68);
            const float4* b1 = (const float4*)(sm + (MP+j0+12)*68);
            float s00 = 0.f, s01 = 0.f, s10 = 0.f, s11 = 0.f;
            #pragma unroll
            for (int q = 0; q < 16; q++) {
                float4 A0 = a0[q], A1 = a1[q], B0 = b0[q], B1 = b1[q];
                s00 += (fminf(A0.x,B0.x) + fminf(A0.y,B0.y)) + (fminf(A0.z,B0.z) + fminf(A0.w,B0.w));
                s01 += (fminf(A0.x,B1.x) + fminf(A0.y,B1.y)) + (fminf(A0.z,B1.z) + fminf(A0.w,B1.w));
                s10 += (fminf(A1.x,B0.x) + fminf(A1.y,B0.y)) + (fminf(A1.z,B0.z) + fminf(A1.w,B0.w));
                s11 += (fminf(A1.x,B1.x) + fminf(A1.y,B1.y)) + (fminf(A1.z,B1.z) + fminf(A1.w,B1.w));
            }
            int pb = b*MP*MG;
            atomicAdd(&g_inter[pb +  i0     *MG + j0     ], s00);
            atomicAdd(&g_inter[pb +  i0     *MG + j0 + 12], s01);
            atomicAdd(&g_inter[pb + (i0+20) *MG + j0     ], s10);
            atomicAdd(&g_inter[pb + (i0+20) *MG + j0 + 12], s11);
        }
    }
    cudaTriggerProgrammaticLaunchCompletion();
}

// =====================================================================
// Kernel C: combine + exist mask (union = Sa + Sb - inter)
// =====================================================================
__global__ void k_final(const float* __restrict__ exist, float* __restrict__ out) {
    cudaGridDependencySynchronize();   // wait for k_B
    int p = blockIdx.x*256 + threadIdx.x;
    if (p < NPAIR) {
        int b = p / (MP*MG);
        int r = p % (MP*MG);
        int i = r / MG, j = r % MG;
        float I  = g_inter[p];
        float U  = g_msum[b*MP + i] + g_msum[BATCH*MP + b*MG + j] - I;
        float ov = 1.0f - I / (U + 1e-8f);
        float cost = g_partial[p] + 2.0f*ov;
        out[p] = (exist[b*MG + j] > 0.5f) ? cost : 0.0f;
    }
}

// ---------------- launch: serial chain with PDL edges ----------------
extern "C" void kernel_launch(void* const* d_in, const int* in_sizes, int n_in,
                              void* d_out, int out_size) {
    const float* pred  = (const float*)d_in[0];
    const float* gt    = (const float*)d_in[1];
    const float* vis   = (const float*)d_in[2];
    const float* exist = (const float*)d_in[3];
    float* out = (float*)d_out;

    k_A<<<128 + 128*MCHUNKS, 128>>>(pred, gt, vis);

    cudaLaunchAttribute attr[1];
    attr[0].id = cudaLaunchAttributeProgrammaticStreamSerialization;
    attr[0].val.programmaticStreamSerializationAllowed = 1;

    {   // k_B with programmatic dependent launch
        cudaLaunchConfig_t cfg = {};
        cfg.gridDim  = dim3(768, 1, 1);
        cfg.blockDim = dim3(256, 1, 1);
        cfg.dynamicSmemBytes = 0;
        cfg.stream = 0;
        cfg.attrs = attr;
        cfg.numAttrs = 1;
        cudaLaunchKernelEx(&cfg, k_B);
    }
    {   // k_final with programmatic dependent launch
        cudaLaunchConfig_t cfg = {};
        cfg.gridDim  = dim3((NPAIR + 255)/256, 1, 1);
        cfg.blockDim = dim3(256, 1, 1);
        cfg.dynamicSmemBytes = 0;
        cfg.stream = 0;
        cfg.attrs = attr;
        cfg.numAttrs = 1;
        cudaLaunchKernelEx(&cfg, k_final, exist, out);
    }
}

// round 15
// speedup vs baseline: 1.0051x; 1.0051x over previous
#include <cuda_runtime.h>
#include <math.h>

#define BATCH 2
#define MP 40
#define MG 24
#define NPT 24
#define NRS 64
#define Hh 72
#define Ww 128
#define GRID_N (Hh*Ww)      // 9216
#define NPAIR (BATCH*MP*MG) // 1920
#define BIG2 1e18f
#define THICKF 0.03f
#define SHARPF 80.0f

// ---------------- device scratch ----------------
__device__ float g_prs [BATCH*MP*NRS*2];
__device__ float g_grs [BATCH*MG*NRS*2];
__device__ float g_ptan[BATCH*MP*NRS*2];
__device__ float g_gtan[BATCH*MG*NRS*2];
__device__ float g_pmask[BATCH*MP*GRID_N];
__device__ float g_gmask[BATCH*MG*GRID_N];
__device__ float g_partial[NPAIR];
__device__ float g_inter[NPAIR];
__device__ float g_msum[128];

__device__ __forceinline__ float sl1(float d) {
    d = fabsf(d);
    return d < 1.f ? 0.5f*d*d : d - 0.5f;
}

// =====================================================================
// Kernel A (128 threads/block, 1280 blocks): CHAMPION CONFIG (frozen)
//   blocks 0..127:    resample + tangents (one curve per block)
//   blocks 128..1279: soft masks; curve=(bid-128)/9, chunk=(bid-128)%9,
//                     8 rows per thread
//   zeroes g_inter and g_msum for kernel B
// =====================================================================
__global__ void __launch_bounds__(128, 10)
k_A(const float* __restrict__ pred,
    const float* __restrict__ gt,
    const float* __restrict__ vis) {
    int bid = blockIdx.x, tid = threadIdx.x;
    int gtid = bid*128 + tid;
    if (gtid < NPAIR) g_inter[gtid] = 0.f;
    if (gtid >= NPAIR && gtid < NPAIR + 128) g_msum[gtid - NPAIR] = 0.f;

    if (bid < 128) {
        // ---------------- resample + tangents ----------------
        __shared__ float px[NPT], py[NPT], pm[NPT], cum[NPT];
        __shared__ float ox[NRS], oy[NRS];
        int cid = bid;
        bool isPred = cid < BATCH*MP;
        const float* src; float *dst_rs, *dst_tan; int b, c;
        if (isPred) {
            b = cid / MP; c = cid % MP;
            src = pred + (b*MP + c)*NPT*2;
            dst_rs  = g_prs  + (b*MP + c)*NRS*2;
            dst_tan = g_ptan + (b*MP + c)*NRS*2;
        } else {
            int q = cid - BATCH*MP;
            b = q / MG; c = q % MG;
            src = gt + (b*MG + c)*NPT*2;
            dst_rs  = g_grs  + (b*MG + c)*NRS*2;
            dst_tan = g_gtan + (b*MG + c)*NRS*2;
        }
        if (tid < NPT) {
            px[tid] = src[tid*2];
            py[tid] = src[tid*2+1];
            pm[tid] = isPred ? 1.0f : (vis[(b*MG+c)*NPT + tid] > 0.5f ? 1.0f : 0.0f);
        }
        __syncthreads();
        if (tid == 0) {
            if (!isPred) {
                int cnt = 0;
                for (int k = 0; k < NPT; k++) cnt += (pm[k] > 0.5f);
                if (cnt < 2) for (int k = 0; k < NPT; k++) pm[k] = 1.0f;
            }
            float s = 0.f; cum[0] = 0.f;
            for (int k = 0; k < NPT-1; k++) {
                float dx = px[k+1]-px[k], dy = py[k+1]-py[k];
                s += sqrtf(dx*dx+dy*dy) * (pm[k]*pm[k+1]);
                cum[k+1] = s;
            }
        }
        __syncthreads();
        if (tid < NRS) {
            float total = cum[NPT-1];
            float qx, qy;
            if (total < 1e-8f) { qx = px[0]; qy = py[0]; }
            else {
                float t = (tid == NRS-1) ? total : tid * (1.0f/(NRS-1)) * total;
                int cnt = 0;
                for (int k = 0; k < NPT; k++) cnt += (cum[k] <= t);
                int idx = cnt - 1;
                if (idx > NPT-2) idx = NPT-2;
                if (idx < 0)     idx = 0;
                float lt = cum[idx], rt = cum[idx+1];
                float alpha = (t - lt) / fmaxf(rt - lt, 1e-8f);
                qx = px[idx] + alpha*(px[idx+1]-px[idx]);
                qy = py[idx] + alpha*(py[idx+1]-py[idx]);
            }
            ox[tid] = qx; oy[tid] = qy;
            dst_rs[tid*2]   = qx;
            dst_rs[tid*2+1] = qy;
        }
        __syncthreads();
        if (tid < NRS) {
            int a = (tid == 0)     ? 0     : tid-1;
            int e = (tid == NRS-1) ? NRS-1 : tid+1;
            float fx = ox[e]-ox[a], fy = oy[e]-oy[a];
            float nr = fmaxf(sqrtf(fx*fx+fy*fy), 1e-8f);
            dst_tan[tid*2]   = fx/nr;
            dst_tan[tid*2+1] = fy/nr;
        }
    } else {
        // ---------------- soft mask: column-constant X, 8 rows/thread ----------------
        int mb = bid - 128;
        int cid = mb / 9, chunk = mb % 9;
        __shared__ float px[NPT], py[NPT], pm[NPT], sppen[NPT];
        __shared__ __align__(16) float4 s4a[NPT-1];
        __shared__ __align__(16) float4 s4b[NPT-1];
        __shared__ int s_any;

        bool isPred = cid < BATCH*MP;
        const float* src; float* dst; int b, c;
        if (isPred) {
            b = cid/MP; c = cid%MP;
            src = pred + (b*MP+c)*NPT*2;
            dst = g_pmask + (b*MP+c)*GRID_N;
        } else {
            int q = cid - BATCH*MP;
            b = q/MG; c = q%MG;
            src = gt + (b*MG+c)*NPT*2;
            dst = g_gmask + (b*MG+c)*GRID_N;
        }
        if (tid < NPT) {
            px[tid] = src[tid*2];
            py[tid] = src[tid*2+1];
            pm[tid] = isPred ? 1.f : (vis[(b*MG+c)*NPT+tid] > 0.5f ? 1.f : 0.f);
        }
        __syncthreads();
        if (tid == 0) {
            if (!isPred) {
                int cnt = 0;
                for (int k = 0; k < NPT; k++) cnt += (pm[k] > 0.5f);
                if (cnt < 2) for (int k = 0; k < NPT; k++) pm[k] = 1.f;
            }
            int any = 0;
            for (int k = 0; k < NPT-1; k++) any |= (pm[k]*pm[k+1] > 0.5f);
            s_any = any;
        }
        __syncthreads();
        if (tid < NPT-1) {
            float ax = px[tid], ay = py[tid];
            float abx = px[tid+1]-ax, aby = py[tid+1]-ay;
            float inv = 1.0f / fmaxf(abx*abx + aby*aby, 1e-8f);
            s4a[tid] = make_float4(ax, ay, abx, aby);
            s4b[tid] = make_float4(abx*inv, aby*inv, (ax*abx + ay*aby)*inv,
                                   (pm[tid]*pm[tid+1] > 0.5f) ? 0.f : BIG2);
        }
        if (tid < NPT) sppen[tid] = (pm[tid] > 0.5f) ? 0.f : BIG2;
        __syncthreads();

        float X = tid * (1.0f/(Ww-1));
        int row0 = chunk*8;
        float m[8];
        #pragma unroll
        for (int k = 0; k < 8; k++) m[k] = BIG2;

        if (s_any) {
            #pragma unroll 1
            for (int s = 0; s < NPT-1; s++) {
                float4 A = s4a[s];
                float4 B = s4b[s];
                float e   = fmaf(X, B.x, -B.z);
                float dxs = X - A.x;
                #pragma unroll
                for (int k = 0; k < 8; k++) {
                    float Y = (row0 + k) * (1.0f/(Hh-1));
                    float t = __saturatef(fmaf(Y, B.y, e));
                    float dx = fmaf(-t, A.z, dxs);
                    float dy = fmaf(-t, A.w, Y - A.y);
                    float d2 = fmaf(dy, dy, fmaf(dx, dx, B.w));
                    m[k] = fminf(m[k], d2);
                }
            }
        } else {
            #pragma unroll 1
            for (int p = 0; p < NPT; p++) {
                float ax = px[p], ay = py[p];
                float dxs = X - ax;
                float sxp = fmaf(dxs, dxs, sppen[p]);
                #pragma unroll
                for (int k = 0; k < 8; k++) {
                    float dy = (row0 + k) * (1.0f/(Hh-1)) - ay;
                    m[k] = fminf(m[k], fmaf(dy, dy, sxp));
                }
            }
        }
        #pragma unroll
        for (int k = 0; k < 8; k++) {
            float z = (THICKF - sqrtf(m[k])) * SHARPF;
            dst[(row0 + k)*128 + tid] = __fdividef(1.0f, 1.0f + __expf(-z));
        }
    }
    cudaTriggerProgrammaticLaunchCompletion();
}

// =====================================================================
// Kernel B (1248 blocks x 256 thr):
//   [blocks 0..959]    pair costs: 2 pairs/block, 128 threads per pair,
//                      thread 2n+half covers point n / segment-half half
//   [blocks 960..1247] IoU min-sums (64-pt chunks, 2x2 tiling) + msum
// =====================================================================
#define GSTRIDE 1280
__global__ void __launch_bounds__(256, 6)
k_B() {
    __shared__ __align__(16) float sm[4384];   // 17536 B (IoU needs 64*68=4352)
    int bid = blockIdx.x, tid = threadIdx.x;

    cudaGridDependencySynchronize();   // wait for k_A's writes to be visible

    if (bid < 960) {
        // ---------------- pair costs: split-segment, 128 thr/pair ----------------
        int grp = tid >> 7, tg = tid & 127;
        int pid = bid*2 + grp;
        int b = pid / (MP*MG);
        int r = pid % (MP*MG);
        int i = r / MG, j = r % MG;

        float* gp  = sm + grp*GSTRIDE;
        float* spx = gp;        float* spy = gp + 64;
        float* sgx = gp + 128;  float* sgy = gp + 192;
        float4* psa = (float4*)(gp + 256);
        float4* psb = (float4*)(gp + 508);
        float4* gsa = (float4*)(gp + 760);
        float4* gsb = (float4*)(gp + 1012);
        float* red  = gp + 1264;   // 12 floats

        const float* pr = g_prs + (b*MP+i)*NRS*2;
        const float* gr = g_grs + (b*MG+j)*NRS*2;
        if (tg < 64) { spx[tg] = pr[2*tg]; spy[tg] = pr[2*tg+1]; }
        else         { int u = tg-64; sgx[u] = gr[2*u]; sgy[u] = gr[2*u+1]; }

        int n = tg >> 1, half = tg & 1;
        float ptx_ = 0.f, pty_ = 0.f, gtx_ = 0.f, gty_ = 0.f;
        if (half == 0) {
            const float* pt  = g_ptan + (b*MP+i)*NRS*2;
            const float* gtt = g_gtan + (b*MG+j)*NRS*2;
            ptx_ = pt[2*n];  pty_ = pt[2*n+1];
            gtx_ = gtt[2*n]; gty_ = gtt[2*n+1];
        }
        __syncthreads();
        if (tg < NRS-1) {
            float ax = spx[tg], ay = spy[tg];
            float abx = spx[tg+1]-ax, aby = spy[tg+1]-ay;
            float inv = 1.0f / fmaxf(abx*abx+aby*aby, 1e-8f);
            psa[tg] = make_float4(ax, ay, abx, aby);
            psb[tg] = make_float4(abx*inv, aby*inv, (ax*abx+ay*aby)*inv, 0.f);
        } else if (tg >= 64 && tg < 64 + NRS-1) {
            int u = tg - 64;
            float ax = sgx[u], ay = sgy[u];
            float abx = sgx[u+1]-ax, aby = sgy[u+1]-ay;
            float inv = 1.0f / fmaxf(abx*abx+aby*aby, 1e-8f);
            gsa[u] = make_float4(ax, ay, abx, aby);
            gsb[u] = make_float4(abx*inv, aby*inv, (ax*abx+ay*aby)*inv, 0.f);
        }
        __syncthreads();

        float qx = spx[n], qy = spy[n], ux = sgx[n], uy = sgy[n];
        float da2 = BIG2, db2 = BIG2;
        int s0 = half*32;
        int s1 = half ? (NRS-1) : 32;     // [0,32) or [32,63)
        #pragma unroll 4
        for (int s = s0; s < s1; s++) {
            {
                float4 A = gsa[s], B = gsb[s];
                float t = __saturatef(fmaf(qy, B.y, fmaf(qx, B.x, -B.z)));
                float dx = fmaf(-t, A.z, qx - A.x);
                float dy = fmaf(-t, A.w, qy - A.y);
                da2 = fminf(da2, fmaf(dy, dy, dx*dx));
            }
            {
                float4 A = psa[s], B = psb[s];
                float t = __saturatef(fmaf(uy, B.y, fmaf(ux, B.x, -B.z)));
                float dx = fmaf(-t, A.z, ux - A.x);
                float dy = fmaf(-t, A.w, uy - A.y);
                db2 = fminf(db2, fmaf(dy, dy, dx*dx));
            }
        }
        unsigned msk = 0xffffffffu;
        da2 = fminf(da2, __shfl_xor_sync(msk, da2, 1));
        db2 = fminf(db2, __shfl_xor_sync(msk, db2, 1));

        float dd = 0.f, td = 0.f, cv = 0.f;
        if (half == 0) {
            dd = sqrtf(da2) + sqrtf(db2);
            td = fabsf(ptx_*gtx_ + pty_*gty_);
            if (n < NRS-2) {
                float psx = spx[n+2] - 2.f*spx[n+1] + spx[n];
                float psy = spy[n+2] - 2.f*spy[n+1] + spy[n];
                float gsxv = sgx[n+2] - 2.f*sgx[n+1] + sgx[n];
                float gsyv = sgy[n+2] - 2.f*sgy[n+1] + sgy[n];
                cv = sl1(psx-gsxv) + sl1(psy-gsyv);
            }
        }
        #pragma unroll
        for (int o = 16; o; o >>= 1) {
            dd += __shfl_down_sync(msk, dd, o);
            td += __shfl_down_sync(msk, td, o);
            cv += __shfl_down_sync(msk, cv, o);
        }
        int w = (tg >> 5), l = tg & 31;
        if (l == 0) { red[w*3+0]=dd; red[w*3+1]=td; red[w*3+2]=cv; }
        __syncthreads();
        if (tg == 0) {
            float sdd  = red[0] + red[3] + red[6] + red[9];
            float std_ = red[1] + red[4] + red[7] + red[10];
            float scv  = red[2] + red[5] + red[8] + red[11];
            float sym  = 0.5f * sdd * (1.0f/NRS);
            float tanv = 1.0f - std_ * (1.0f/NRS);
            float curv = scv * (1.0f/((NRS-2)*2));
            g_partial[pid] = 5.0f*sym + 1.0f*tanv + 0.5f*curv;
        }
    } else {
        // ---------------- IoU min-sums over 64-pt grid chunk ----------------
        int blk = bid - 960;
        int b  = blk / 144;
        int ch = blk % 144;
        int gbase = ch * 64;

        for (int idx = tid; idx < 64*64; idx += 256) {
            int c = idx >> 6, g = idx & 63;
            float v = (c < MP) ? g_pmask[(b*MP + c)*GRID_N + gbase + g]
                               : g_gmask[(b*MG + (c-MP))*GRID_N + gbase + g];
            sm[c*68 + g] = v;
        }
        __syncthreads();

        if (tid < 64) {
            const float4* row = (const float4*)(sm + tid*68);
            float s = 0.f;
            #pragma unroll
            for (int q = 0; q < 16; q++) {
                float4 v = row[q];
                s += (v.x + v.y) + (v.z + v.w);
            }
            int mi = (tid < MP) ? (b*MP + tid) : (BATCH*MP + b*MG + (tid - MP));
            atomicAdd(&g_msum[mi], s);
        }

        if (tid < 240) {
            int i0 = tid / 12, j0 = tid % 12;
            const float4* a0 = (const float4*)(sm + i0*68);
            const float4* a1 = (const float4*)(sm + (i0+20)*68);
            const float4* b0 = (const float4*)(sm + (MP+j0)*68);
            const float4* b1 = (const float4*)(sm + (MP+j0+12)*68);
            float s00 = 0.f, s01 = 0.f, s10 = 0.f, s11 = 0.f;
            #pragma unroll
            for (int q = 0; q < 16; q++) {
                float4 A0 = a0[q], A1 = a1[q], B0 = b0[q], B1 = b1[q];
                s00 += (fminf(A0.x,B0.x) + fminf(A0.y,B0.y)) + (fminf(A0.z,B0.z) + fminf(A0.w,B0.w));
                s01 += (fminf(A0.x,B1.x) + fminf(A0.y,B1.y)) + (fminf(A0.z,B1.z) + fminf(A0.w,B1.w));
                s10 += (fminf(A1.x,B0.x) + fminf(A1.y,B0.y)) + (fminf(A1.z,B0.z) + fminf(A1.w,B0.w));
                s11 += (fminf(A1.x,B1.x) + fminf(A1.y,B1.y)) + (fminf(A1.z,B1.z) + fminf(A1.w,B1.w));
            }
            int pb = b*MP*MG;
            atomicAdd(&g_inter[pb +  i0     *MG + j0     ], s00);
            atomicAdd(&g_inter[pb +  i0     *MG + j0 + 12], s01);
            atomicAdd(&g_inter[pb + (i0+20) *MG + j0     ], s10);
            atomicAdd(&g_inter[pb + (i0+20) *MG + j0 + 12], s11);
        }
    }
    cudaTriggerProgrammaticLaunchCompletion();
}

// =====================================================================
// Kernel C: combine + exist mask (union = Sa + Sb - inter)
// =====================================================================
__global__ void k_final(const float* __restrict__ exist, float* __restrict__ out) {
    cudaGridDependencySynchronize();   // wait for k_B
    int p = blockIdx.x*256 + threadIdx.x;
    if (p < NPAIR) {
        int b = p / (MP*MG);
        int r = p % (MP*MG);
        int i = r / MG, j = r % MG;
        float I  = g_inter[p];
        float U  = g_msum[b*MP + i] + g_msum[BATCH*MP + b*MG + j] - I;
        float ov = 1.0f - I / (U + 1e-8f);
        float cost = g_partial[p] + 2.0f*ov;
        out[p] = (exist[b*MG + j] > 0.5f) ? cost : 0.0f;
    }
}

// ---------------- launch: serial chain with PDL edges ----------------
extern "C" void kernel_launch(void* const* d_in, const int* in_sizes, int n_in,
                              void* d_out, int out_size) {
    const float* pred  = (const float*)d_in[0];
    const float* gt    = (const float*)d_in[1];
    const float* vis   = (const float*)d_in[2];
    const float* exist = (const float*)d_in[3];
    float* out = (float*)d_out;

    k_A<<<1280, 128>>>(pred, gt, vis);

    cudaLaunchAttribute attr[1];
    attr[0].id = cudaLaunchAttributeProgrammaticStreamSerialization;
    attr[0].val.programmaticStreamSerializationAllowed = 1;

    {   // k_B with programmatic dependent launch
        cudaLaunchConfig_t cfg = {};
        cfg.gridDim  = dim3(1248, 1, 1);
        cfg.blockDim = dim3(256, 1, 1);
        cfg.dynamicSmemBytes = 0;
        cfg.stream = 0;
        cfg.attrs = attr;
        cfg.numAttrs = 1;
        cudaLaunchKernelEx(&cfg, k_B);
    }
    {   // k_final with programmatic dependent launch
        cudaLaunchConfig_t cfg = {};
        cfg.gridDim  = dim3((NPAIR + 255)/256, 1, 1);
        cfg.blockDim = dim3(256, 1, 1);
        cfg.dynamicSmemBytes = 0;
        cfg.stream = 0;
        cfg.attrs = attr;
        cfg.numAttrs = 1;
        cudaLaunchKernelEx(&cfg, k_final, exist, out);
    }
}

// round 16
// speedup vs baseline: 1.0571x; 1.0517x over previous
#include <cuda_runtime.h>
#include <math.h>

#define BATCH 2
#define MP 40
#define MG 24
#define NPT 24
#define NRS 64
#define Hh 72
#define Ww 128
#define GRID_N (Hh*Ww)      // 9216
#define NPAIR (BATCH*MP*MG) // 1920
#define BIG2 1e18f
#define THICKF 0.03f
#define SHARPF 80.0f

// mask decomposition: 6 chunks x 12 rows per thread
#define MCHUNKS 6
#define MROWS 12

// ---------------- device scratch ----------------
__device__ float g_prs [BATCH*MP*NRS*2];
__device__ float g_grs [BATCH*MG*NRS*2];
__device__ float g_ptan[BATCH*MP*NRS*2];
__device__ float g_gtan[BATCH*MG*NRS*2];
__device__ float g_pmask[BATCH*MP*GRID_N];
__device__ float g_gmask[BATCH*MG*GRID_N];
__device__ float g_partial[NPAIR];
__device__ float g_inter[NPAIR];
__device__ float g_msum[128];

__device__ __forceinline__ float sl1(float d) {
    d = fabsf(d);
    return d < 1.f ? 0.5f*d*d : d - 0.5f;
}

// =====================================================================
// Kernel A (128 threads/block, 896 blocks):
//   blocks 0..127:   resample + tangents (one curve per block)
//   blocks 128..895: soft masks; curve=(bid-128)/6, chunk=(bid-128)%6,
//                    12 rows per thread (max per-segment amortization)
//   zeroes g_inter and g_msum for kernel B
// =====================================================================
__global__ void __launch_bounds__(128, 8)
k_A(const float* __restrict__ pred,
    const float* __restrict__ gt,
    const float* __restrict__ vis) {
    int bid = blockIdx.x, tid = threadIdx.x;
    int gtid = bid*128 + tid;
    if (gtid < NPAIR) g_inter[gtid] = 0.f;
    if (gtid >= NPAIR && gtid < NPAIR + 128) g_msum[gtid - NPAIR] = 0.f;

    if (bid < 128) {
        // ---------------- resample + tangents ----------------
        __shared__ float px[NPT], py[NPT], pm[NPT], cum[NPT];
        __shared__ float ox[NRS], oy[NRS];
        int cid = bid;
        bool isPred = cid < BATCH*MP;
        const float* src; float *dst_rs, *dst_tan; int b, c;
        if (isPred) {
            b = cid / MP; c = cid % MP;
            src = pred + (b*MP + c)*NPT*2;
            dst_rs  = g_prs  + (b*MP + c)*NRS*2;
            dst_tan = g_ptan + (b*MP + c)*NRS*2;
        } else {
            int q = cid - BATCH*MP;
            b = q / MG; c = q % MG;
            src = gt + (b*MG + c)*NPT*2;
            dst_rs  = g_grs  + (b*MG + c)*NRS*2;
            dst_tan = g_gtan + (b*MG + c)*NRS*2;
        }
        if (tid < NPT) {
            px[tid] = src[tid*2];
            py[tid] = src[tid*2+1];
            pm[tid] = isPred ? 1.0f : (vis[(b*MG+c)*NPT + tid] > 0.5f ? 1.0f : 0.0f);
        }
        __syncthreads();
        if (tid == 0) {
            if (!isPred) {
                int cnt = 0;
                for (int k = 0; k < NPT; k++) cnt += (pm[k] > 0.5f);
                if (cnt < 2) for (int k = 0; k < NPT; k++) pm[k] = 1.0f;
            }
            float s = 0.f; cum[0] = 0.f;
            for (int k = 0; k < NPT-1; k++) {
                float dx = px[k+1]-px[k], dy = py[k+1]-py[k];
                s += sqrtf(dx*dx+dy*dy) * (pm[k]*pm[k+1]);
                cum[k+1] = s;
            }
        }
        __syncthreads();
        if (tid < NRS) {
            float total = cum[NPT-1];
            float qx, qy;
            if (total < 1e-8f) { qx = px[0]; qy = py[0]; }
            else {
                float t = (tid == NRS-1) ? total : tid * (1.0f/(NRS-1)) * total;
                int cnt = 0;
                for (int k = 0; k < NPT; k++) cnt += (cum[k] <= t);
                int idx = cnt - 1;
                if (idx > NPT-2) idx = NPT-2;
                if (idx < 0)     idx = 0;
                float lt = cum[idx], rt = cum[idx+1];
                float alpha = (t - lt) / fmaxf(rt - lt, 1e-8f);
                qx = px[idx] + alpha*(px[idx+1]-px[idx]);
                qy = py[idx] + alpha*(py[idx+1]-py[idx]);
            }
            ox[tid] = qx; oy[tid] = qy;
            dst_rs[tid*2]   = qx;
            dst_rs[tid*2+1] = qy;
        }
        __syncthreads();
        if (tid < NRS) {
            int a = (tid == 0)     ? 0     : tid-1;
            int e = (tid == NRS-1) ? NRS-1 : tid+1;
            float fx = ox[e]-ox[a], fy = oy[e]-oy[a];
            float nr = fmaxf(sqrtf(fx*fx+fy*fy), 1e-8f);
            dst_tan[tid*2]   = fx/nr;
            dst_tan[tid*2+1] = fy/nr;
        }
    } else {
        // ---------------- soft mask: column-constant X, 12 rows/thread ----------------
        int mb = bid - 128;
        int cid = mb / MCHUNKS, chunk = mb % MCHUNKS;
        __shared__ float px[NPT], py[NPT], pm[NPT], sppen[NPT];
        __shared__ __align__(16) float4 s4a[NPT-1];
        __shared__ __align__(16) float4 s4b[NPT-1];
        __shared__ int s_any;

        bool isPred = cid < BATCH*MP;
        const float* src; float* dst; int b, c;
        if (isPred) {
            b = cid/MP; c = cid%MP;
            src = pred + (b*MP+c)*NPT*2;
            dst = g_pmask + (b*MP+c)*GRID_N;
        } else {
            int q = cid - BATCH*MP;
            b = q/MG; c = q%MG;
            src = gt + (b*MG+c)*NPT*2;
            dst = g_gmask + (b*MG+c)*GRID_N;
        }
        if (tid < NPT) {
            px[tid] = src[tid*2];
            py[tid] = src[tid*2+1];
            pm[tid] = isPred ? 1.f : (vis[(b*MG+c)*NPT+tid] > 0.5f ? 1.f : 0.f);
        }
        __syncthreads();
        if (tid == 0) {
            if (!isPred) {
                int cnt = 0;
                for (int k = 0; k < NPT; k++) cnt += (pm[k] > 0.5f);
                if (cnt < 2) for (int k = 0; k < NPT; k++) pm[k] = 1.f;
            }
            int any = 0;
            for (int k = 0; k < NPT-1; k++) any |= (pm[k]*pm[k+1] > 0.5f);
            s_any = any;
        }
        __syncthreads();
        if (tid < NPT-1) {
            float ax = px[tid], ay = py[tid];
            float abx = px[tid+1]-ax, aby = py[tid+1]-ay;
            float inv = 1.0f / fmaxf(abx*abx + aby*aby, 1e-8f);
            s4a[tid] = make_float4(ax, ay, abx, aby);
            s4b[tid] = make_float4(abx*inv, aby*inv, (ax*abx + ay*aby)*inv,
                                   (pm[tid]*pm[tid+1] > 0.5f) ? 0.f : BIG2);
        }
        if (tid < NPT) sppen[tid] = (pm[tid] > 0.5f) ? 0.f : BIG2;
        __syncthreads();

        float X = tid * (1.0f/(Ww-1));
        int row0 = chunk*MROWS;
        float m[MROWS];
        #pragma unroll
        for (int k = 0; k < MROWS; k++) m[k] = BIG2;

        if (s_any) {
            #pragma unroll 1
            for (int s = 0; s < NPT-1; s++) {
                float4 A = s4a[s];
                float4 B = s4b[s];
                float e   = fmaf(X, B.x, -B.z);
                float dxs = X - A.x;
                #pragma unroll
                for (int k = 0; k < MROWS; k++) {
                    float Y = (row0 + k) * (1.0f/(Hh-1));
                    float t = __saturatef(fmaf(Y, B.y, e));
                    float dx = fmaf(-t, A.z, dxs);
                    float dy = fmaf(-t, A.w, Y - A.y);
                    float d2 = fmaf(dy, dy, fmaf(dx, dx, B.w));
                    m[k] = fminf(m[k], d2);
                }
            }
        } else {
            #pragma unroll 1
            for (int p = 0; p < NPT; p++) {
                float ax = px[p], ay = py[p];
                float dxs = X - ax;
                float sxp = fmaf(dxs, dxs, sppen[p]);
                #pragma unroll
                for (int k = 0; k < MROWS; k++) {
                    float dy = (row0 + k) * (1.0f/(Hh-1)) - ay;
                    m[k] = fminf(m[k], fmaf(dy, dy, sxp));
                }
            }
        }
        #pragma unroll
        for (int k = 0; k < MROWS; k++) {
            float z = (THICKF - sqrtf(m[k])) * SHARPF;
            dst[(row0 + k)*128 + tid] = __fdividef(1.0f, 1.0f + __expf(-z));
        }
    }
    cudaTriggerProgrammaticLaunchCompletion();
}

// =====================================================================
// Kernel B (768 blocks x 256 thr): CHAMPION CONFIG (frozen, R13)
//   [blocks 0..479]   pairwise sym/tan/curv (4 pairs per block)
//   [blocks 480..767] IoU min-sums (64-pt chunks, 2x2 tiling) + msum
// =====================================================================
#define GSTRIDE 1272
__global__ void __launch_bounds__(256, 6)
k_B() {
    __shared__ __align__(16) float sm[4*GSTRIDE];   // 20352 B
    int bid = blockIdx.x, tid = threadIdx.x;

    cudaGridDependencySynchronize();   // wait for k_A's writes to be visible

    if (bid < 480) {
        // ---------------- pair costs ----------------
        int grp = tid >> 6, n = tid & 63;
        int pid = bid*4 + grp;
        int b = pid / (MP*MG);
        int r = pid % (MP*MG);
        int i = r / MG, j = r % MG;

        float* gp  = sm + grp*GSTRIDE;
        float* spx = gp;        float* spy = gp + 64;
        float* sgx = gp + 128;  float* sgy = gp + 192;
        float4* psa = (float4*)(gp + 256);
        float4* psb = (float4*)(gp + 508);
        float4* gsa = (float4*)(gp + 760);
        float4* gsb = (float4*)(gp + 1012);
        float* red  = gp + 1264;

        const float* pr = g_prs + (b*MP+i)*NRS*2;
        const float* gr = g_grs + (b*MG+j)*NRS*2;
        spx[n] = pr[2*n]; spy[n] = pr[2*n+1];
        sgx[n] = gr[2*n]; sgy[n] = gr[2*n+1];

        const float* pt  = g_ptan + (b*MP+i)*NRS*2;
        const float* gtt = g_gtan + (b*MG+j)*NRS*2;
        float ptx_ = pt[2*n],  pty_ = pt[2*n+1];
        float gtx_ = gtt[2*n], gty_ = gtt[2*n+1];

        __syncthreads();
        if (n < NRS-1) {
            float ax = spx[n], ay = spy[n];
            float abx = spx[n+1]-ax, aby = spy[n+1]-ay;
            float inv = 1.0f / fmaxf(abx*abx+aby*aby, 1e-8f);
            psa[n] = make_float4(ax, ay, abx, aby);
            psb[n] = make_float4(abx*inv, aby*inv, (ax*abx+ay*aby)*inv, 0.f);
            ax = sgx[n]; ay = sgy[n];
            abx = sgx[n+1]-ax; aby = sgy[n+1]-ay;
            inv = 1.0f / fmaxf(abx*abx+aby*aby, 1e-8f);
            gsa[n] = make_float4(ax, ay, abx, aby);
            gsb[n] = make_float4(abx*inv, aby*inv, (ax*abx+ay*aby)*inv, 0.f);
        }
        __syncthreads();

        float qx = spx[n], qy = spy[n], ux = sgx[n], uy = sgy[n];
        float da2a = BIG2, da2b = BIG2, db2a = BIG2, db2b = BIG2;
        #pragma unroll 2
        for (int s = 0; s < NRS-2; s += 2) {
            {
                float4 A = gsa[s], B = gsb[s];
                float t = __saturatef(fmaf(qy, B.y, fmaf(qx, B.x, -B.z)));
                float dx = fmaf(-t, A.z, qx - A.x);
                float dy = fmaf(-t, A.w, qy - A.y);
                da2a = fminf(da2a, fmaf(dy, dy, dx*dx));
            }
            {
                float4 A = psa[s], B = psb[s];
                float t = __saturatef(fmaf(uy, B.y, fmaf(ux, B.x, -B.z)));
                float dx = fmaf(-t, A.z, ux - A.x);
                float dy = fmaf(-t, A.w, uy - A.y);
                db2a = fminf(db2a, fmaf(dy, dy, dx*dx));
            }
            {
                float4 A = gsa[s+1], B = gsb[s+1];
                float t = __saturatef(fmaf(qy, B.y, fmaf(qx, B.x, -B.z)));
                float dx = fmaf(-t, A.z, qx - A.x);
                float dy = fmaf(-t, A.w, qy - A.y);
                da2b = fminf(da2b, fmaf(dy, dy, dx*dx));
            }
            {
                float4 A = psa[s+1], B = psb[s+1];
                float t = __saturatef(fmaf(uy, B.y, fmaf(ux, B.x, -B.z)));
                float dx = fmaf(-t, A.z, ux - A.x);
                float dy = fmaf(-t, A.w, uy - A.y);
                db2b = fminf(db2b, fmaf(dy, dy, dx*dx));
            }
        }
        {   // tail segment s = 62
            const int s = NRS-2;
            {
                float4 A = gsa[s], B = gsb[s];
                float t = __saturatef(fmaf(qy, B.y, fmaf(qx, B.x, -B.z)));
                float dx = fmaf(-t, A.z, qx - A.x);
                float dy = fmaf(-t, A.w, qy - A.y);
                da2a = fminf(da2a, fmaf(dy, dy, dx*dx));
            }
            {
                float4 A = psa[s], B = psb[s];
                float t = __saturatef(fmaf(uy, B.y, fmaf(ux, B.x, -B.z)));
                float dx = fmaf(-t, A.z, ux - A.x);
                float dy = fmaf(-t, A.w, uy - A.y);
                db2a = fminf(db2a, fmaf(dy, dy, dx*dx));
            }
        }
        float dd = sqrtf(fminf(da2a, da2b)) + sqrtf(fminf(db2a, db2b));

        float td = fabsf(ptx_*gtx_ + pty_*gty_);

        float cv = 0.f;
        if (n < NRS-2) {
            float psx = spx[n+2] - 2.f*spx[n+1] + spx[n];
            float psy = spy[n+2] - 2.f*spy[n+1] + spy[n];
            float gsxv = sgx[n+2] - 2.f*sgx[n+1] + sgx[n];
            float gsyv = sgy[n+2] - 2.f*sgy[n+1] + sgy[n];
            cv = sl1(psx-gsxv) + sl1(psy-gsyv);
        }
        unsigned msk = 0xffffffffu;
        #pragma unroll
        for (int o = 16; o; o >>= 1) {
            dd += __shfl_down_sync(msk, dd, o);
            td += __shfl_down_sync(msk, td, o);
            cv += __shfl_down_sync(msk, cv, o);
        }
        int w = (n >> 5), l = n & 31;
        if (l == 0) { red[w*3+0]=dd; red[w*3+1]=td; red[w*3+2]=cv; }
        __syncthreads();
        if (n == 0) {
            float sdd  = red[0] + red[3];
            float std_ = red[1] + red[4];
            float scv  = red[2] + red[5];
            float sym  = 0.5f * sdd * (1.0f/NRS);
            float tanv = 1.0f - std_ * (1.0f/NRS);
            float curv = scv * (1.0f/((NRS-2)*2));
            g_partial[pid] = 5.0f*sym + 1.0f*tanv + 0.5f*curv;
        }
    } else {
        // ---------------- IoU min-sums over 64-pt grid chunk ----------------
        int blk = bid - 480;
        int b  = blk / 144;
        int ch = blk % 144;
        int gbase = ch * 64;

        for (int idx = tid; idx < 64*64; idx += 256) {
            int c = idx >> 6, g = idx & 63;
            float v = (c < MP) ? g_pmask[(b*MP + c)*GRID_N + gbase + g]
                               : g_gmask[(b*MG + (c-MP))*GRID_N + gbase + g];
            sm[c*68 + g] = v;
        }
        __syncthreads();

        if (tid < 64) {
            const float4* row = (const float4*)(sm + tid*68);
            float s = 0.f;
            #pragma unroll
            for (int q = 0; q < 16; q++) {
                float4 v = row[q];
                s += (v.x + v.y) + (v.z + v.w);
            }
            int mi = (tid < MP) ? (b*MP + tid) : (BATCH*MP + b*MG + (tid - MP));
            atomicAdd(&g_msum[mi], s);
        }

        if (tid < 240) {
            int i0 = tid / 12, j0 = tid % 12;
            const float4* a0 = (const float4*)(sm + i0*68);
            const float4* a1 = (const float4*)(sm + (i0+20)*68);
            const float4* b0 = (const float4*)(sm + (MP+j0)*68);
            const float4* b1 = (const float4*)(sm + (MP+j0+12)*68);
            float s00 = 0.f, s01 = 0.f, s10 = 0.f, s11 = 0.f;
            #pragma unroll
            for (int q = 0; q < 16; q++) {
                float4 A0 = a0[q], A1 = a1[q], B0 = b0[q], B1 = b1[q];
                s00 += (fminf(A0.x,B0.x) + fminf(A0.y,B0.y)) + (fminf(A0.z,B0.z) + fminf(A0.w,B0.w));
                s01 += (fminf(A0.x,B1.x) + fminf(A0.y,B1.y)) + (fminf(A0.z,B1.z) + fminf(A0.w,B1.w));
                s10 += (fminf(A1.x,B0.x) + fminf(A1.y,B0.y)) + (fminf(A1.z,B0.z) + fminf(A1.w,B0.w));
                s11 += (fminf(A1.x,B1.x) + fminf(A1.y,B1.y)) + (fminf(A1.z,B1.z) + fminf(A1.w,B1.w));
            }
            int pb = b*MP*MG;
            atomicAdd(&g_inter[pb +  i0     *MG + j0     ], s00);
            atomicAdd(&g_inter[pb +  i0     *MG + j0 + 12], s01);
            atomicAdd(&g_inter[pb + (i0+20) *MG + j0     ], s10);
            atomicAdd(&g_inter[pb + (i0+20) *MG + j0 + 12], s11);
        }
    }
    cudaTriggerProgrammaticLaunchCompletion();
}

// =====================================================================
// Kernel C: combine + exist mask (union = Sa + Sb - inter)
// =====================================================================
__global__ void k_final(const float* __restrict__ exist, float* __restrict__ out) {
    cudaGridDependencySynchronize();   // wait for k_B
    int p = blockIdx.x*256 + threadIdx.x;
    if (p < NPAIR) {
        int b = p / (MP*MG);
        int r = p % (MP*MG);
        int i = r / MG, j = r % MG;
        float I  = g_inter[p];
        float U  = g_msum[b*MP + i] + g_msum[BATCH*MP + b*MG + j] - I;
        float ov = 1.0f - I / (U + 1e-8f);
        float cost = g_partial[p] + 2.0f*ov;
        out[p] = (exist[b*MG + j] > 0.5f) ? cost : 0.0f;
    }
}

// ---------------- launch: serial chain with PDL edges ----------------
extern "C" void kernel_launch(void* const* d_in, const int* in_sizes, int n_in,
                              void* d_out, int out_size) {
    const float* pred  = (const float*)d_in[0];
    const float* gt    = (const float*)d_in[1];
    const float* vis   = (const float*)d_in[2];
    const float* exist = (const float*)d_in[3];
    float* out = (float*)d_out;

    k_A<<<128 + 128*MCHUNKS, 128>>>(pred, gt, vis);

    cudaLaunchAttribute attr[1];
    attr[0].id = cudaLaunchAttributeProgrammaticStreamSerialization;
    attr[0].val.programmaticStreamSerializationAllowed = 1;

    {   // k_B with programmatic dependent launch
        cudaLaunchConfig_t cfg = {};
        cfg.gridDim  = dim3(768, 1, 1);
        cfg.blockDim = dim3(256, 1, 1);
        cfg.dynamicSmemBytes = 0;
        cfg.stream = 0;
        cfg.attrs = attr;
        cfg.numAttrs = 1;
        cudaLaunchKernelEx(&cfg, k_B);
    }
    {   // k_final with programmatic dependent launch
        cudaLaunchConfig_t cfg = {};
        cfg.gridDim  = dim3((NPAIR + 255)/256, 1, 1);
        cfg.blockDim = dim3(256, 1, 1);
        cfg.dynamicSmemBytes = 0;
        cfg.stream = 0;
        cfg.attrs = attr;
        cfg.numAttrs = 1;
        cudaLaunchKernelEx(&cfg, k_final, exist, out);
    }
}

// round 17
// speedup vs baseline: 1.0757x; 1.0175x over previous
#include <cuda_runtime.h>
#include <math.h>

#define BATCH 2
#define MP 40
#define MG 24
#define NPT 24
#define NRS 64
#define Hh 72
#define Ww 128
#define GRID_N (Hh*Ww)      // 9216
#define NPAIR (BATCH*MP*MG) // 1920
#define BIG2 1e18f
#define THICKF 0.03f
#define SHARPF 80.0f

// mask decomposition: 6 chunks x 12 rows per thread
#define MCHUNKS 6
#define MROWS 12

// k_B layout: IoU blocks first, then pair blocks
#define NB_IOU 288
#define NB_KB  768

// ---------------- device scratch ----------------
__device__ float g_prs [BATCH*MP*NRS*2];
__device__ float g_grs [BATCH*MG*NRS*2];
__device__ float g_ptan[BATCH*MP*NRS*2];
__device__ float g_gtan[BATCH*MG*NRS*2];
__device__ float g_pmask[BATCH*MP*GRID_N];
__device__ float g_gmask[BATCH*MG*GRID_N];
__device__ float g_partial[NPAIR];
__device__ float g_inter[NPAIR];
__device__ float g_msum[128];

__device__ __forceinline__ float sl1(float d) {
    d = fabsf(d);
    return d < 1.f ? 0.5f*d*d : d - 0.5f;
}

// =====================================================================
// Kernel A (128 threads/block, 896 blocks): CHAMPION CONFIG (frozen)
//   blocks 0..127:   resample + tangents (one curve per block)
//   blocks 128..895: soft masks; curve=(bid-128)/6, chunk=(bid-128)%6,
//                    12 rows per thread
//   zeroes g_inter and g_msum for kernel B
// =====================================================================
__global__ void __launch_bounds__(128, 8)
k_A(const float* __restrict__ pred,
    const float* __restrict__ gt,
    const float* __restrict__ vis) {
    int bid = blockIdx.x, tid = threadIdx.x;
    int gtid = bid*128 + tid;
    if (gtid < NPAIR) g_inter[gtid] = 0.f;
    if (gtid >= NPAIR && gtid < NPAIR + 128) g_msum[gtid - NPAIR] = 0.f;

    if (bid < 128) {
        // ---------------- resample + tangents ----------------
        __shared__ float px[NPT], py[NPT], pm[NPT], cum[NPT];
        __shared__ float ox[NRS], oy[NRS];
        int cid = bid;
        bool isPred = cid < BATCH*MP;
        const float* src; float *dst_rs, *dst_tan; int b, c;
        if (isPred) {
            b = cid / MP; c = cid % MP;
            src = pred + (b*MP + c)*NPT*2;
            dst_rs  = g_prs  + (b*MP + c)*NRS*2;
            dst_tan = g_ptan + (b*MP + c)*NRS*2;
        } else {
            int q = cid - BATCH*MP;
            b = q / MG; c = q % MG;
            src = gt + (b*MG + c)*NPT*2;
            dst_rs  = g_grs  + (b*MG + c)*NRS*2;
            dst_tan = g_gtan + (b*MG + c)*NRS*2;
        }
        if (tid < NPT) {
            px[tid] = src[tid*2];
            py[tid] = src[tid*2+1];
            pm[tid] = isPred ? 1.0f : (vis[(b*MG+c)*NPT + tid] > 0.5f ? 1.0f : 0.0f);
        }
        __syncthreads();
        if (tid == 0) {
            if (!isPred) {
                int cnt = 0;
                for (int k = 0; k < NPT; k++) cnt += (pm[k] > 0.5f);
                if (cnt < 2) for (int k = 0; k < NPT; k++) pm[k] = 1.0f;
            }
            float s = 0.f; cum[0] = 0.f;
            for (int k = 0; k < NPT-1; k++) {
                float dx = px[k+1]-px[k], dy = py[k+1]-py[k];
                s += sqrtf(dx*dx+dy*dy) * (pm[k]*pm[k+1]);
                cum[k+1] = s;
            }
        }
        __syncthreads();
        if (tid < NRS) {
            float total = cum[NPT-1];
            float qx, qy;
            if (total < 1e-8f) { qx = px[0]; qy = py[0]; }
            else {
                float t = (tid == NRS-1) ? total : tid * (1.0f/(NRS-1)) * total;
                int cnt = 0;
                for (int k = 0; k < NPT; k++) cnt += (cum[k] <= t);
                int idx = cnt - 1;
                if (idx > NPT-2) idx = NPT-2;
                if (idx < 0)     idx = 0;
                float lt = cum[idx], rt = cum[idx+1];
                float alpha = (t - lt) / fmaxf(rt - lt, 1e-8f);
                qx = px[idx] + alpha*(px[idx+1]-px[idx]);
                qy = py[idx] + alpha*(py[idx+1]-py[idx]);
            }
            ox[tid] = qx; oy[tid] = qy;
            dst_rs[tid*2]   = qx;
            dst_rs[tid*2+1] = qy;
        }
        __syncthreads();
        if (tid < NRS) {
            int a = (tid == 0)     ? 0     : tid-1;
            int e = (tid == NRS-1) ? NRS-1 : tid+1;
            float fx = ox[e]-ox[a], fy = oy[e]-oy[a];
            float nr = fmaxf(sqrtf(fx*fx+fy*fy), 1e-8f);
            dst_tan[tid*2]   = fx/nr;
            dst_tan[tid*2+1] = fy/nr;
        }
    } else {
        // ---------------- soft mask: column-constant X, 12 rows/thread ----------------
        int mb = bid - 128;
        int cid = mb / MCHUNKS, chunk = mb % MCHUNKS;
        __shared__ float px[NPT], py[NPT], pm[NPT], sppen[NPT];
        __shared__ __align__(16) float4 s4a[NPT-1];
        __shared__ __align__(16) float4 s4b[NPT-1];
        __shared__ int s_any;

        bool isPred = cid < BATCH*MP;
        const float* src; float* dst; int b, c;
        if (isPred) {
            b = cid/MP; c = cid%MP;
            src = pred + (b*MP+c)*NPT*2;
            dst = g_pmask + (b*MP+c)*GRID_N;
        } else {
            int q = cid - BATCH*MP;
            b = q/MG; c = q%MG;
            src = gt + (b*MG+c)*NPT*2;
            dst = g_gmask + (b*MG+c)*GRID_N;
        }
        if (tid < NPT) {
            px[tid] = src[tid*2];
            py[tid] = src[tid*2+1];
            pm[tid] = isPred ? 1.f : (vis[(b*MG+c)*NPT+tid] > 0.5f ? 1.f : 0.f);
        }
        __syncthreads();
        if (tid == 0) {
            if (!isPred) {
                int cnt = 0;
                for (int k = 0; k < NPT; k++) cnt += (pm[k] > 0.5f);
                if (cnt < 2) for (int k = 0; k < NPT; k++) pm[k] = 1.f;
            }
            int any = 0;
            for (int k = 0; k < NPT-1; k++) any |= (pm[k]*pm[k+1] > 0.5f);
            s_any = any;
        }
        __syncthreads();
        if (tid < NPT-1) {
            float ax = px[tid], ay = py[tid];
            float abx = px[tid+1]-ax, aby = py[tid+1]-ay;
            float inv = 1.0f / fmaxf(abx*abx + aby*aby, 1e-8f);
            s4a[tid] = make_float4(ax, ay, abx, aby);
            s4b[tid] = make_float4(abx*inv, aby*inv, (ax*abx + ay*aby)*inv,
                                   (pm[tid]*pm[tid+1] > 0.5f) ? 0.f : BIG2);
        }
        if (tid < NPT) sppen[tid] = (pm[tid] > 0.5f) ? 0.f : BIG2;
        __syncthreads();

        float X = tid * (1.0f/(Ww-1));
        int row0 = chunk*MROWS;
        float m[MROWS];
        #pragma unroll
        for (int k = 0; k < MROWS; k++) m[k] = BIG2;

        if (s_any) {
            #pragma unroll 1
            for (int s = 0; s < NPT-1; s++) {
                float4 A = s4a[s];
                float4 B = s4b[s];
                float e   = fmaf(X, B.x, -B.z);
                float dxs = X - A.x;
                #pragma unroll
                for (int k = 0; k < MROWS; k++) {
                    float Y = (row0 + k) * (1.0f/(Hh-1));
                    float t = __saturatef(fmaf(Y, B.y, e));
                    float dx = fmaf(-t, A.z, dxs);
                    float dy = fmaf(-t, A.w, Y - A.y);
                    float d2 = fmaf(dy, dy, fmaf(dx, dx, B.w));
                    m[k] = fminf(m[k], d2);
                }
            }
        } else {
            #pragma unroll 1
            for (int p = 0; p < NPT; p++) {
                float ax = px[p], ay = py[p];
                float dxs = X - ax;
                float sxp = fmaf(dxs, dxs, sppen[p]);
                #pragma unroll
                for (int k = 0; k < MROWS; k++) {
                    float dy = (row0 + k) * (1.0f/(Hh-1)) - ay;
                    m[k] = fminf(m[k], fmaf(dy, dy, sxp));
                }
            }
        }
        #pragma unroll
        for (int k = 0; k < MROWS; k++) {
            float z = (THICKF - sqrtf(m[k])) * SHARPF;
            dst[(row0 + k)*128 + tid] = __fdividef(1.0f, 1.0f + __expf(-z));
        }
    }
    cudaTriggerProgrammaticLaunchCompletion();
}

// =====================================================================
// Kernel B (768 blocks x 256 thr): IoU blocks FIRST (early L2 warmup),
//   pair blocks after.
//   [blocks 0..287]   IoU min-sums (64-pt chunks, 2x2 tiling) + msum
//   [blocks 288..767] pairwise sym/tan/curv (4 pairs per block)
// =====================================================================
#define GSTRIDE 1272
__global__ void __launch_bounds__(256, 6)
k_B() {
    __shared__ __align__(16) float sm[4*GSTRIDE];   // 20352 B
    int bid = blockIdx.x, tid = threadIdx.x;

    cudaGridDependencySynchronize();   // wait for k_A's writes to be visible

    if (bid >= NB_IOU) {
        // ---------------- pair costs ----------------
        int grp = tid >> 6, n = tid & 63;
        int pid = (bid - NB_IOU)*4 + grp;
        int b = pid / (MP*MG);
        int r = pid % (MP*MG);
        int i = r / MG, j = r % MG;

        float* gp  = sm + grp*GSTRIDE;
        float* spx = gp;        float* spy = gp + 64;
        float* sgx = gp + 128;  float* sgy = gp + 192;
        float4* psa = (float4*)(gp + 256);
        float4* psb = (float4*)(gp + 508);
        float4* gsa = (float4*)(gp + 760);
        float4* gsb = (float4*)(gp + 1012);
        float* red  = gp + 1264;

        const float* pr = g_prs + (b*MP+i)*NRS*2;
        const float* gr = g_grs + (b*MG+j)*NRS*2;
        spx[n] = pr[2*n]; spy[n] = pr[2*n+1];
        sgx[n] = gr[2*n]; sgy[n] = gr[2*n+1];

        const float* pt  = g_ptan + (b*MP+i)*NRS*2;
        const float* gtt = g_gtan + (b*MG+j)*NRS*2;
        float ptx_ = pt[2*n],  pty_ = pt[2*n+1];
        float gtx_ = gtt[2*n], gty_ = gtt[2*n+1];

        __syncthreads();
        if (n < NRS-1) {
            float ax = spx[n], ay = spy[n];
            float abx = spx[n+1]-ax, aby = spy[n+1]-ay;
            float inv = 1.0f / fmaxf(abx*abx+aby*aby, 1e-8f);
            psa[n] = make_float4(ax, ay, abx, aby);
            psb[n] = make_float4(abx*inv, aby*inv, (ax*abx+ay*aby)*inv, 0.f);
            ax = sgx[n]; ay = sgy[n];
            abx = sgx[n+1]-ax; aby = sgy[n+1]-ay;
            inv = 1.0f / fmaxf(abx*abx+aby*aby, 1e-8f);
            gsa[n] = make_float4(ax, ay, abx, aby);
            gsb[n] = make_float4(abx*inv, aby*inv, (ax*abx+ay*aby)*inv, 0.f);
        }
        __syncthreads();

        float qx = spx[n], qy = spy[n], ux = sgx[n], uy = sgy[n];
        float da2a = BIG2, da2b = BIG2, db2a = BIG2, db2b = BIG2;
        #pragma unroll 2
        for (int s = 0; s < NRS-2; s += 2) {
            {
                float4 A = gsa[s], B = gsb[s];
                float t = __saturatef(fmaf(qy, B.y, fmaf(qx, B.x, -B.z)));
                float dx = fmaf(-t, A.z, qx - A.x);
                float dy = fmaf(-t, A.w, qy - A.y);
                da2a = fminf(da2a, fmaf(dy, dy, dx*dx));
            }
            {
                float4 A = psa[s], B = psb[s];
                float t = __saturatef(fmaf(uy, B.y, fmaf(ux, B.x, -B.z)));
                float dx = fmaf(-t, A.z, ux - A.x);
                float dy = fmaf(-t, A.w, uy - A.y);
                db2a = fminf(db2a, fmaf(dy, dy, dx*dx));
            }
            {
                float4 A = gsa[s+1], B = gsb[s+1];
                float t = __saturatef(fmaf(qy, B.y, fmaf(qx, B.x, -B.z)));
                float dx = fmaf(-t, A.z, qx - A.x);
                float dy = fmaf(-t, A.w, qy - A.y);
                da2b = fminf(da2b, fmaf(dy, dy, dx*dx));
            }
            {
                float4 A = psa[s+1], B = psb[s+1];
                float t = __saturatef(fmaf(uy, B.y, fmaf(ux, B.x, -B.z)));
                float dx = fmaf(-t, A.z, ux - A.x);
                float dy = fmaf(-t, A.w, uy - A.y);
                db2b = fminf(db2b, fmaf(dy, dy, dx*dx));
            }
        }
        {   // tail segment s = 62
            const int s = NRS-2;
            {
                float4 A = gsa[s], B = gsb[s];
                float t = __saturatef(fmaf(qy, B.y, fmaf(qx, B.x, -B.z)));
                float dx = fmaf(-t, A.z, qx - A.x);
                float dy = fmaf(-t, A.w, qy - A.y);
                da2a = fminf(da2a, fmaf(dy, dy, dx*dx));
            }
            {
                float4 A = psa[s], B = psb[s];
                float t = __saturatef(fmaf(uy, B.y, fmaf(ux, B.x, -B.z)));
                float dx = fmaf(-t, A.z, ux - A.x);
                float dy = fmaf(-t, A.w, uy - A.y);
                db2a = fminf(db2a, fmaf(dy, dy, dx*dx));
            }
        }
        float dd = sqrtf(fminf(da2a, da2b)) + sqrtf(fminf(db2a, db2b));

        float td = fabsf(ptx_*gtx_ + pty_*gty_);

        float cv = 0.f;
        if (n < NRS-2) {
            float psx = spx[n+2] - 2.f*spx[n+1] + spx[n];
            float psy = spy[n+2] - 2.f*spy[n+1] + spy[n];
            float gsxv = sgx[n+2] - 2.f*sgx[n+1] + sgx[n];
            float gsyv = sgy[n+2] - 2.f*sgy[n+1] + sgy[n];
            cv = sl1(psx-gsxv) + sl1(psy-gsyv);
        }
        unsigned msk = 0xffffffffu;
        #pragma unroll
        for (int o = 16; o; o >>= 1) {
            dd += __shfl_down_sync(msk, dd, o);
            td += __shfl_down_sync(msk, td, o);
            cv += __shfl_down_sync(msk, cv, o);
        }
        int w = (n >> 5), l = n & 31;
        if (l == 0) { red[w*3+0]=dd; red[w*3+1]=td; red[w*3+2]=cv; }
        __syncthreads();
        if (n == 0) {
            float sdd  = red[0] + red[3];
            float std_ = red[1] + red[4];
            float scv  = red[2] + red[5];
            float sym  = 0.5f * sdd * (1.0f/NRS);
            float tanv = 1.0f - std_ * (1.0f/NRS);
            float curv = scv * (1.0f/((NRS-2)*2));
            g_partial[pid] = 5.0f*sym + 1.0f*tanv + 0.5f*curv;
        }
    } else {
        // ---------------- IoU min-sums over 64-pt grid chunk ----------------
        int blk = bid;
        int b  = blk / 144;
        int ch = blk % 144;
        int gbase = ch * 64;

        for (int idx = tid; idx < 64*64; idx += 256) {
            int c = idx >> 6, g = idx & 63;
            float v = (c < MP) ? g_pmask[(b*MP + c)*GRID_N + gbase + g]
                               : g_gmask[(b*MG + (c-MP))*GRID_N + gbase + g];
            sm[c*68 + g] = v;
        }
        __syncthreads();

        if (tid < 64) {
            const float4* row = (const float4*)(sm + tid*68);
            float s = 0.f;
            #pragma unroll
            for (int q = 0; q < 16; q++) {
                float4 v = row[q];
                s += (v.x + v.y) + (v.z + v.w);
            }
            int mi = (tid < MP) ? (b*MP + tid) : (BATCH*MP + b*MG + (tid - MP));
            atomicAdd(&g_msum[mi], s);
        }

        if (tid < 240) {
            int i0 = tid / 12, j0 = tid % 12;
            const float4* a0 = (const float4*)(sm + i0*68);
            const float4* a1 = (const float4*)(sm + (i0+20)*68);
            const float4* b0 = (const float4*)(sm + (MP+j0)*68);
            const float4* b1 = (const float4*)(sm + (MP+j0+12)*68);
            float s00 = 0.f, s01 = 0.f, s10 = 0.f, s11 = 0.f;
            #pragma unroll
            for (int q = 0; q < 16; q++) {
                float4 A0 = a0[q], A1 = a1[q], B0 = b0[q], B1 = b1[q];
                s00 += (fminf(A0.x,B0.x) + fminf(A0.y,B0.y)) + (fminf(A0.z,B0.z) + fminf(A0.w,B0.w));
                s01 += (fminf(A0.x,B1.x) + fminf(A0.y,B1.y)) + (fminf(A0.z,B1.z) + fminf(A0.w,B1.w));
                s10 += (fminf(A1.x,B0.x) + fminf(A1.y,B0.y)) + (fminf(A1.z,B0.z) + fminf(A1.w,B0.w));
                s11 += (fminf(A1.x,B1.x) + fminf(A1.y,B1.y)) + (fminf(A1.z,B1.z) + fminf(A1.w,B1.w));
            }
            int pb = b*MP*MG;
            atomicAdd(&g_inter[pb +  i0     *MG + j0     ], s00);
            atomicAdd(&g_inter[pb +  i0     *MG + j0 + 12], s01);
            atomicAdd(&g_inter[pb + (i0+20) *MG + j0     ], s10);
            atomicAdd(&g_inter[pb + (i0+20) *MG + j0 + 12], s11);
        }
    }
    cudaTriggerProgrammaticLaunchCompletion();
}

// =====================================================================
// Kernel C: combine + exist mask (union = Sa + Sb - inter)
// =====================================================================
__global__ void k_final(const float* __restrict__ exist, float* __restrict__ out) {
    cudaGridDependencySynchronize();   // wait for k_B
    int p = blockIdx.x*256 + threadIdx.x;
    if (p < NPAIR) {
        int b = p / (MP*MG);
        int r = p % (MP*MG);
        int i = r / MG, j = r % MG;
        float I  = g_inter[p];
        float U  = g_msum[b*MP + i] + g_msum[BATCH*MP + b*MG + j] - I;
        float ov = 1.0f - I / (U + 1e-8f);
        float cost = g_partial[p] + 2.0f*ov;
        out[p] = (exist[b*MG + j] > 0.5f) ? cost : 0.0f;
    }
}

// ---------------- launch: serial chain with PDL edges ----------------
extern "C" void kernel_launch(void* const* d_in, const int* in_sizes, int n_in,
                              void* d_out, int out_size) {
    const float* pred  = (const float*)d_in[0];
    const float* gt    = (const float*)d_in[1];
    const float* vis   = (const float*)d_in[2];
    const float* exist = (const float*)d_in[3];
    float* out = (float*)d_out;

    k_A<<<128 + 128*MCHUNKS, 128>>>(pred, gt, vis);

    cudaLaunchAttribute attr[1];
    attr[0].id = cudaLaunchAttributeProgrammaticStreamSerialization;
    attr[0].val.programmaticStreamSerializationAllowed = 1;

    {   // k_B with programmatic dependent launch
        cudaLaunchConfig_t cfg = {};
        cfg.gridDim  = dim3(NB_KB, 1, 1);
        cfg.blockDim = dim3(256, 1, 1);
        cfg.dynamicSmemBytes = 0;
        cfg.stream = 0;
        cfg.attrs = attr;
        cfg.numAttrs = 1;
        cudaLaunchKernelEx(&cfg, k_B);
    }
    {   // k_final with programmatic dependent launch
        cudaLaunchConfig_t cfg = {};
        cfg.gridDim  = dim3((NPAIR + 255)/256, 1, 1);
        cfg.blockDim = dim3(256, 1, 1);
        cfg.dynamicSmemBytes = 0;
        cfg.stream = 0;
        cfg.attrs = attr;
        cfg.numAttrs = 1;
        cudaLaunchKernelEx(&cfg, k_final, exist, out);
    }
}